// round 1
// baseline (speedup 1.0000x reference)
#include <cuda_runtime.h>
#include <cuda_bf16.h>
#include <cstdint>

// ---------------------------------------------------------------------------
// GCN layer: out = relu(diag(d) * A_tilde * diag(d) * H * W),  d = rowsum(A)^-1/2
// Reassociated as:  P = diag(d) * (H @ W)   (small GEMM, 8192x256x256)
//                   out = relu(diag(d) * (A @ P))  (big GEMM, 8192x256x8192)
// Big GEMM is fp32 compute-bound -> use packed fma.rn.f32x2 (2x FFMA tput).
// ---------------------------------------------------------------------------

#define NROWS 8192
#define FDIM  256

__device__ float g_d[NROWS];
__device__ float g_P[NROWS * FDIM];

// ---------------- packed f32x2 helpers ----------------
__device__ __forceinline__ uint64_t pack2dup(float v) {
    uint64_t r;
    asm("mov.b64 %0, {%1, %2};" : "=l"(r) : "f"(v), "f"(v));
    return r;
}
__device__ __forceinline__ uint64_t fma2(uint64_t a, uint64_t b, uint64_t c) {
    uint64_t d;
    asm("fma.rn.f32x2 %0, %1, %2, %3;" : "=l"(d) : "l"(a), "l"(b), "l"(c));
    return d;
}
__device__ __forceinline__ void unpack2(uint64_t v, float& lo, float& hi) {
    asm("mov.b64 {%0, %1}, %2;" : "=f"(lo), "=f"(hi) : "l"(v));
}

// ---------------- row-sum -> d = rsqrt(sum) ----------------
__global__ __launch_bounds__(256) void rowsum_kernel(const float* __restrict__ A,
                                                     float* __restrict__ d, int N) {
    __shared__ float red[8];
    const int row = blockIdx.x;
    const float4* Ar = (const float4*)(A + (size_t)row * N);
    const int n4 = N >> 2;
    float s = 0.f;
    for (int i = threadIdx.x; i < n4; i += 256) {
        float4 v = Ar[i];
        s += (v.x + v.y) + (v.z + v.w);
    }
    #pragma unroll
    for (int o = 16; o; o >>= 1) s += __shfl_xor_sync(0xffffffffu, s, o);
    if ((threadIdx.x & 31) == 0) red[threadIdx.x >> 5] = s;
    __syncthreads();
    if (threadIdx.x < 8) {
        s = red[threadIdx.x];
        #pragma unroll
        for (int o = 4; o; o >>= 1) s += __shfl_xor_sync(0xffu, s, o);
        if (threadIdx.x == 0) d[row] = rsqrtf(s);
    }
}

// ---------------- tiled SGEMM with row-scale (+optional relu) epilogue ------
// C[M,N] = epi( dvec[row] * (A[M,K] @ B[K,N]) ),  all row-major.
// BM=128, BN=64, BK=16; 256 threads; per-thread 8(M) x 4(N) via packed f32x2
// pairs along M (so A-side pairs load directly as 8B words from smem).
#define BM 128
#define BN 64
#define BK 16
#define TM 8
#define TN 4

template <int RELU>
__global__ __launch_bounds__(256) void gemm_scaled(const float* __restrict__ A,
                                                   const float* __restrict__ B,
                                                   const float* __restrict__ dvec,
                                                   float* __restrict__ C,
                                                   int M, int N, int K) {
    __shared__ float As[BK][BM];   // transposed A tile: As[k][m]
    __shared__ float Bs[BK][BN];

    const int tid = threadIdx.x;
    const int tx = tid & 15;   // N direction (0..15)
    const int ty = tid >> 4;   // M direction (0..15)
    const int bm = blockIdx.y * BM;
    const int bn = blockIdx.x * BN;

    // A tile load mapping: 128 rows x 16 cols, 2 threads/row, 8 floats each
    const int arow = tid >> 1;          // 0..127
    const int acol = (tid & 1) << 3;    // 0 or 8
    const float* Ap = A + (size_t)(bm + arow) * K + acol;

    // B tile load mapping: 16 rows x 64 cols, 1 float4/thread
    const int brow = tid >> 4;          // 0..15
    const int bcol = (tid & 15) << 2;   // 0..60
    const float* Bp = B + (size_t)brow * N + bn + bcol;

    uint64_t acc[4][TN];                // packed pairs of M-rows
    #pragma unroll
    for (int i = 0; i < 4; i++)
        #pragma unroll
        for (int j = 0; j < TN; j++) acc[i][j] = 0ull;  // (0.f, 0.f)

    // prefetch tile 0
    float4 pa0 = *(const float4*)(Ap);
    float4 pa1 = *(const float4*)(Ap + 4);
    float4 pb  = *(const float4*)(Bp);

    for (int kt = 0; kt < K; kt += BK) {
        // commit prefetched tile to smem (A transposed)
        As[acol + 0][arow] = pa0.x; As[acol + 1][arow] = pa0.y;
        As[acol + 2][arow] = pa0.z; As[acol + 3][arow] = pa0.w;
        As[acol + 4][arow] = pa1.x; As[acol + 5][arow] = pa1.y;
        As[acol + 6][arow] = pa1.z; As[acol + 7][arow] = pa1.w;
        *(float4*)&Bs[brow][bcol] = pb;
        __syncthreads();

        const int ktn = kt + BK;
        if (ktn < K) {
            pa0 = *(const float4*)(Ap + ktn);
            pa1 = *(const float4*)(Ap + ktn + 4);
            pb  = *(const float4*)(Bp + (size_t)ktn * N);
        }

        #pragma unroll
        for (int k = 0; k < BK; k++) {
            // 8 consecutive M-rows as 4 packed f32x2 words (16B-aligned LDS)
            const ulonglong2 a01 = *(const ulonglong2*)&As[k][ty * TM];
            const ulonglong2 a23 = *(const ulonglong2*)&As[k][ty * TM + 4];
            const uint64_t av[4] = {a01.x, a01.y, a23.x, a23.y};
            const float4 bv = *(const float4*)&Bs[k][tx * TN];
            uint64_t bb[4];
            bb[0] = pack2dup(bv.x); bb[1] = pack2dup(bv.y);
            bb[2] = pack2dup(bv.z); bb[3] = pack2dup(bv.w);
            #pragma unroll
            for (int i = 0; i < 4; i++)
                #pragma unroll
                for (int j = 0; j < 4; j++)
                    acc[i][j] = fma2(av[i], bb[j], acc[i][j]);
        }
        __syncthreads();
    }

    // epilogue: scale by dvec[row], optional relu, vectorized stores
    const int ccol = bn + tx * TN;
    #pragma unroll
    for (int i = 0; i < 4; i++) {
        const int r0 = bm + ty * TM + 2 * i;
        const float s0 = dvec[r0];
        const float s1 = dvec[r0 + 1];
        float lo[4], hi[4];
        #pragma unroll
        for (int j = 0; j < 4; j++) {
            unpack2(acc[i][j], lo[j], hi[j]);
            lo[j] *= s0; hi[j] *= s1;
            if (RELU) { lo[j] = fmaxf(lo[j], 0.f); hi[j] = fmaxf(hi[j], 0.f); }
        }
        *(float4*)&C[(size_t)r0 * N + ccol]       = make_float4(lo[0], lo[1], lo[2], lo[3]);
        *(float4*)&C[(size_t)(r0 + 1) * N + ccol] = make_float4(hi[0], hi[1], hi[2], hi[3]);
    }
}

// ---------------------------------------------------------------------------
extern "C" void kernel_launch(void* const* d_in, const int* in_sizes, int n_in,
                              void* d_out, int out_size) {
    // Robust input mapping by element count
    const float* H = nullptr;   // 8192*256
    const float* A = nullptr;   // 8192*8192
    const float* W = nullptr;   // 256*256
    for (int i = 0; i < n_in; i++) {
        if (in_sizes[i] == NROWS * NROWS) A = (const float*)d_in[i];
        else if (in_sizes[i] == FDIM * FDIM) W = (const float*)d_in[i];
        else if (in_sizes[i] == NROWS * FDIM) H = (const float*)d_in[i];
    }
    float* out = (float*)d_out;

    float* dptr = nullptr;
    float* Pptr = nullptr;
    cudaGetSymbolAddress((void**)&dptr, g_d);
    cudaGetSymbolAddress((void**)&Pptr, g_P);

    // 1) d = rowsum(A)^-1/2
    rowsum_kernel<<<NROWS, 256>>>(A, dptr, NROWS);

    // 2) P = diag(d) * (H @ W)    [8192 x 256]
    dim3 gridS(FDIM / BN, NROWS / BM);
    gemm_scaled<0><<<gridS, 256>>>(H, W, dptr, Pptr, NROWS, FDIM, FDIM);

    // 3) out = relu(diag(d) * (A @ P))   [8192 x 256], K = 8192
    dim3 gridB(FDIM / BN, NROWS / BM);
    gemm_scaled<1><<<gridB, 256>>>(A, Pptr, dptr, out, NROWS, FDIM, NROWS);
}